// round 16
// baseline (speedup 1.0000x reference)
#include <cuda_runtime.h>
#include <cuda_fp16.h>
#include <stdint.h>

// Problem dims
#define T_ 4
#define B_ 32
#define C_ 512
#define N_ 196            // H*W
#define TB_ 128           // T*B
#define TBCN_ 12845056    // T*B*C*N
#define J_ 25088          // TB*N (GEMM columns), ordered j = (b*196+n)*4 + t

// ---------------- static scratch (allocation-free) ----------------
__device__ __half g_ax[TBCN_];    // x spikes  [j][c]
__device__ __half g_aq[TBCN_];    // q spikes  [j][c]
__device__ __half g_ak[TBCN_];    // k spikes  [j][c]
__device__ __half g_av[TBCN_];    // v spikes  [j][c]
__device__ __half g_wsp[4 * 2 * 262144];  // weight fp16 2-limb splits [mat][s][d*512+c]
__device__ unsigned char g_kvs[TB_ * C_];  // kv spikes [tb][c]

// ================= helpers =================
__device__ __forceinline__ uint32_t smem_u32(const void* p) {
    uint32_t a;
    asm("{ .reg .u64 t; cvta.to.shared.u64 t, %1; cvt.u32.u64 %0, t; }" : "=r"(a) : "l"(p));
    return a;
}
__device__ __forceinline__ void cp16(uint32_t dst, const void* src) {
    asm volatile("cp.async.cg.shared.global [%0], [%1], 16;" :: "r"(dst), "l"(src));
}
#define CP_COMMIT() asm volatile("cp.async.commit_group;" ::: "memory")
#define CP_WAIT1()  asm volatile("cp.async.wait_group 1;" ::: "memory")
#define CP_WAIT0()  asm volatile("cp.async.wait_group 0;" ::: "memory")

__device__ __forceinline__ void ldm_x4(uint32_t addr, uint32_t& r0, uint32_t& r1,
                                       uint32_t& r2, uint32_t& r3) {
    asm volatile("ldmatrix.sync.aligned.m8n8.x4.shared.b16 {%0,%1,%2,%3}, [%4];"
                 : "=r"(r0), "=r"(r1), "=r"(r2), "=r"(r3) : "r"(addr));
}
__device__ __forceinline__ void mma16816(float* c, const uint32_t* a, const uint32_t* b) {
    asm volatile("mma.sync.aligned.m16n8k16.row.col.f32.f16.f16.f32 "
                 "{%0,%1,%2,%3}, {%4,%5,%6,%7}, {%8,%9}, {%0,%1,%2,%3};"
                 : "+f"(c[0]), "+f"(c[1]), "+f"(c[2]), "+f"(c[3])
                 : "r"(a[0]), "r"(a[1]), "r"(a[2]), "r"(a[3]), "r"(b[0]), "r"(b[1]));
}

// smem tile geometry: row stride 40 fp16 (80B) -> ldmatrix conflict-free
#define RS 40
#define B_TILE_B (128 * RS * 2)          // 10240 bytes
#define A_TILE_B (128 * RS * 2)          // per split
#define NSPLIT 2
#define BUF_B (B_TILE_B + NSPLIT * A_TILE_B)  // 30720
#define SMEM_DYN 69632                   // >= 2*BUF_B (61440), >= 128*133*4 (68096), >= 16510*4 (66040)

// ---------------- K0: weight fp16 2-limb split ----------------
__global__ void split_w_kernel(const float* __restrict__ w0, const float* __restrict__ w1,
                               const float* __restrict__ w2, const float* __restrict__ w3,
                               __half* __restrict__ out) {
    int i = blockIdx.x * 256 + threadIdx.x;  // over 4*262144
    int mat = i >> 18;
    int k = i & 262143;
    const float* W = (mat == 0) ? w0 : (mat == 1) ? w1 : (mat == 2) ? w2 : w3;
    float w = W[k];
    __half f0 = __float2half_rn(w);
    float r = w - __half2float(f0);
    __half f1 = __float2half_rn(r);   // fp16 subnormals cover the residual range
    __half* o = out + (size_t)mat * 2 * 262144;
    o[k] = f0;
    o[262144 + k] = f1;
}

// ---------------- K1: shortcut LIF: x[t][b][c][n] -> Ax fp16 [j][c], j=(b*196+n)*4+t ----
__global__ __launch_bounds__(256) void lif_x_kernel(const float* __restrict__ x,
                                                    __half* __restrict__ Ax) {
    __shared__ float xt[16][197];
    __shared__ float vv[16][197];
    int b = blockIdx.x, c0 = blockIdx.y * 16, tid = threadIdx.x;
    for (int i = tid; i < 16 * 197; i += 256) ((float*)vv)[i] = 0.f;
    __syncthreads();
    const __half one = __float2half_rn(1.0f);
    const __half zero = __float2half_rn(0.0f);
    for (int t = 0; t < T_; t++) {
        for (int i = tid; i < 16 * 196; i += 256) {
            int cc = i / 196, n = i - cc * 196;
            xt[cc][n] = x[(size_t)(((t * B_ + b) * C_) + c0 + cc) * N_ + n];
        }
        __syncthreads();
        for (int i = tid; i < 16 * 196; i += 256) {
            int n = i >> 4, cc = i & 15;
            float v = vv[cc][n];
            v += (xt[cc][n] - v) * 0.5f;
            bool s = (v >= 1.0f);
            int j = (b * 196 + n) * 4 + t;
            Ax[(size_t)j * C_ + c0 + cc] = s ? one : zero;
            vv[cc][n] = s ? 0.f : v;
        }
        __syncthreads();
    }
}

// ---------------- K4: kv = sum_n(k&v), LIF over t -> kvs[tb][c] ----------------
// 512 threads: 64 channels x 8 n-chunks -> 2x warp count vs R15 (latency-bound fix).
__global__ __launch_bounds__(512) void kv_lif_kernel(const __half* __restrict__ Ak,
                                                     const __half* __restrict__ Av,
                                                     unsigned char* __restrict__ kvs) {
    __shared__ int red[8][4][64];  // [nq][t][c]
    int b = blockIdx.x, c0 = blockIdx.y * 64;
    int cc = threadIdx.x & 63, q = threadIdx.x >> 6;  // q 0..7
    const unsigned short* ak = (const unsigned short*)Ak;
    const unsigned short* av = (const unsigned short*)Av;
    int nbeg = q * 24 + (q < 4 ? q : 4);   // 25,25,25,25,24,24,24,24
    int ncnt = (q < 4) ? 25 : 24;
    int cnt[4] = {0, 0, 0, 0};
#pragma unroll 6
    for (int i = 0; i < ncnt; i++) {
        int n = nbeg + i;
        size_t base = (size_t)((b * 196 + n) * 4) * C_ + c0 + cc;
#pragma unroll
        for (int t = 0; t < 4; t++)
            cnt[t] += ((ak[base + t * C_] & av[base + t * C_]) != 0);
    }
#pragma unroll
    for (int t = 0; t < 4; t++) red[q][t][cc] = cnt[t];
    __syncthreads();
    if (q == 0) {
        float v = 0.f;
#pragma unroll
        for (int t = 0; t < 4; t++) {
            int s8 = 0;
#pragma unroll
            for (int qq = 0; qq < 8; qq++) s8 += red[qq][t][cc];
            float pre = (float)s8;
            v += (pre - v) * 0.5f;
            bool s = (v >= 1.0f);
            kvs[(t * B_ + b) * C_ + c0 + cc] = (unsigned char)s;
            if (s) v = 0.f;
        }
    }
}

// ---------------- HMMA GEMM ----------------
// QKV (!OUT): P = W_z * Ax, BN, then fused 4-step LIF over adjacent t columns;
//             writes fp16 spikes to Asp[z] (+ vh for z==2).
// OUT:        B operand = Aq masked in-smem by kvs; epilogue BN+bias+residual -> out,
//             smem-staged so gmem loads/stores are n-coalesced.
struct GemmArgs {
    const __half* Bact;
    const __half* W[3];
    const float* g[3];
    const float* bb[3];
    const float* m[3];
    const float* vv[3];
    __half* Asp[3];            // QKV: spike outputs
    float* vh;                 // QKV z==2
    const unsigned char* kvs;  // OUT
    float* out;                // OUT
    const float* bias;         // OUT
    const float* xid;          // OUT
};

template <bool OUT>
__global__ __launch_bounds__(256) void gemm_mma(GemmArgs ga) {
    extern __shared__ char sm[];
    __shared__ float scs[128];
    __shared__ float shs[128];
    uint32_t sb = smem_u32(sm);
    int tid = threadIdx.x, lane = tid & 31, wid = tid >> 5;
    int wd = wid >> 2, wj = wid & 3;            // warps: 2 (d) x 4 (j)
    int j0 = blockIdx.x * 128, d0 = blockIdx.y * 128, z = blockIdx.z;
    const __half* __restrict__ Wz = ga.W[z];
    const __half* __restrict__ Ba = ga.Bact;

    // BN scale/shift
    if (tid < 128) {
        int d = d0 + tid;
        float sc = ga.g[z][d] / sqrtf(ga.vv[z][d] + 1e-5f);
        float sh = ga.bb[z][d] - ga.m[z][d] * sc;
        if (OUT) sh += ga.bias[d] * sc;
        scs[tid] = sc;
        shs[tid] = sh;
    }

    float acc[4][4][4];
#pragma unroll
    for (int a = 0; a < 4; a++)
#pragma unroll
        for (int b = 0; b < 4; b++)
#pragma unroll
            for (int c = 0; c < 4; c++) acc[a][b][c] = 0.f;

    int brow = tid >> 2, bseg = tid & 3;  // B slots: rows brow, brow+64; 8 cols each

    // OUT: per-thread tb of its two B rows (constant across chunks)
    int tb_r[2];
    if (OUT) {
#pragma unroll
        for (int i = 0; i < 2; i++) {
            int j = j0 + brow + i * 64;
            int t = j & 3, g = j >> 2, b = g / 196;
            tb_r[i] = t * B_ + b;
        }
    }

    auto load_chunk = [&](int buf, int it) {
        int c0 = it * 32;
        uint32_t base = sb + buf * BUF_B;
#pragma unroll
        for (int i = 0; i < 2; i++) {
            int row = brow + i * 64;
            cp16(base + row * (RS * 2) + bseg * 16,
                 Ba + (size_t)(j0 + row) * C_ + c0 + bseg * 8);
        }
#pragma unroll
        for (int i = 0; i < 2 * NSPLIT; i++) {
            int e = tid + i * 256;
            int s = e >> 9;
            int row = (e >> 2) & 127;
            int seg = e & 3;
            cp16(base + B_TILE_B + s * A_TILE_B + row * (RS * 2) + seg * 16,
                 Wz + (size_t)s * 262144 + (size_t)(d0 + row) * C_ + c0 + seg * 8);
        }
    };

    // ldmatrix address patterns
    int sub = lane >> 3, l7 = lane & 7;
    int a_r = (sub & 1) * 8 + l7, a_c2 = (sub >> 1) * 8;
    int b_r = (sub >> 1) * 8 + l7, b_c2 = (sub & 1) * 8;

    load_chunk(0, 0);
    CP_COMMIT();

    for (int it = 0; it < 16; it++) {
        if (it < 15) {
            load_chunk((it + 1) & 1, it + 1);
            CP_COMMIT();
            CP_WAIT1();
        } else {
            CP_WAIT0();
        }

        // OUT: mask own B slots with kvs (this thread's own cp.async data, now complete)
        if (OUT) {
            int c0 = it * 32;
#pragma unroll
            for (int i = 0; i < 2; i++) {
                int row = brow + i * 64;
                const unsigned char* kp = ga.kvs + tb_r[i] * C_ + c0 + bseg * 8;
                uint32_t k0 = *(const uint32_t*)kp;
                uint32_t k1 = *(const uint32_t*)(kp + 4);
                uint4* sp = (uint4*)(sm + (it & 1) * BUF_B + row * (RS * 2) + bseg * 16);
                uint4 w = *sp;
                w.x &= ((k0 & 0xFFu) ? 0xFFFFu : 0u) | ((k0 & 0xFF00u) ? 0xFFFF0000u : 0u);
                w.y &= ((k0 & 0xFF0000u) ? 0xFFFFu : 0u) | ((k0 & 0xFF000000u) ? 0xFFFF0000u : 0u);
                w.z &= ((k1 & 0xFFu) ? 0xFFFFu : 0u) | ((k1 & 0xFF00u) ? 0xFFFF0000u : 0u);
                w.w &= ((k1 & 0xFF0000u) ? 0xFFFFu : 0u) | ((k1 & 0xFF000000u) ? 0xFFFF0000u : 0u);
                *sp = w;
            }
        }
        __syncthreads();

        uint32_t base = sb + (it & 1) * BUF_B;
        uint32_t bB = base;
        uint32_t bA = base + B_TILE_B;

        uint32_t bf[2][4][2];
#pragma unroll
        for (int k16 = 0; k16 < 2; k16++)
#pragma unroll
            for (int np = 0; np < 2; np++) {
                int row = wj * 32 + np * 16 + b_r;
                int col = k16 * 16 + b_c2;
                uint32_t addr = bB + row * (RS * 2) + col * 2;
                ldm_x4(addr, bf[k16][np * 2][0], bf[k16][np * 2][1],
                       bf[k16][np * 2 + 1][0], bf[k16][np * 2 + 1][1]);
            }

#pragma unroll
        for (int s = 0; s < NSPLIT; s++) {
#pragma unroll
            for (int k16 = 0; k16 < 2; k16++) {
#pragma unroll
                for (int mi = 0; mi < 4; mi++) {
                    uint32_t af[4];
                    int row = wd * 64 + mi * 16 + a_r;
                    int col = k16 * 16 + a_c2;
                    uint32_t addr = bA + s * A_TILE_B + row * (RS * 2) + col * 2;
                    ldm_x4(addr, af[0], af[1], af[2], af[3]);
#pragma unroll
                    for (int ni = 0; ni < 4; ni++)
                        mma16816(acc[mi][ni], af, bf[k16][ni]);
                }
            }
        }
        __syncthreads();
    }

    // ---------------- epilogue ----------------
    int r = lane >> 2, cq = (lane & 3) * 2;
    if (OUT) {
        // Stage BN'd values to smem S2[(t*32+g)*129 + d] (read conflict-free),
        // then write out/xid n-coalesced (lane = g -> consecutive n).
        float* S2 = (float*)sm;
#pragma unroll
        for (int mi = 0; mi < 4; mi++) {
            int dl0 = wd * 64 + mi * 16 + r;
#pragma unroll
            for (int ni = 0; ni < 4; ni++) {
                int jjl = wj * 32 + ni * 8 + cq;
#pragma unroll
                for (int e = 0; e < 4; e++) {
                    int dd = dl0 + (e >> 1) * 8;
                    int jl = jjl + (e & 1);
                    float v = acc[mi][ni][e] * scs[dd] + shs[dd];
                    int t = jl & 3, g = jl >> 2;
                    S2[(t * 32 + g) * 129 + dd] = v;
                }
            }
        }
        __syncthreads();
        const float* xid = ga.xid;
        float* o = ga.out;
        int g0 = blockIdx.x * 32;
        int gg = g0 + lane;
        int bb2 = gg / 196;
        int nn = gg - bb2 * 196;
#pragma unroll 4
        for (int i = 0; i < 64; i++) {
            int idx = i * 8 + wid;        // 512 (d,t) pairs over 8 warps
            int d = idx >> 2, t = idx & 3;
            float v = S2[(t * 32 + lane) * 129 + d];
            size_t gi = (size_t)((t * B_ + bb2) * C_ + d0 + d) * N_ + nn;
            o[gi] = v + xid[gi];
        }
    } else {
        // stage BN'd pre-acts to smem [d][j_local], stride 133 (odd -> LIF reads
        // conflict-free). Scalar stores only (odd stride => float2 would misalign).
        float* S = (float*)sm;
#pragma unroll
        for (int mi = 0; mi < 4; mi++) {
            int dl0 = wd * 64 + mi * 16 + r;
#pragma unroll
            for (int ni = 0; ni < 4; ni++) {
                int jj = wj * 32 + ni * 8 + cq;
                S[dl0 * 133 + jj] = acc[mi][ni][0] * scs[dl0] + shs[dl0];
                S[dl0 * 133 + jj + 1] = acc[mi][ni][1] * scs[dl0] + shs[dl0];
                S[(dl0 + 8) * 133 + jj] = acc[mi][ni][2] * scs[dl0 + 8] + shs[dl0 + 8];
                S[(dl0 + 8) * 133 + jj + 1] = acc[mi][ni][3] * scs[dl0 + 8] + shs[dl0 + 8];
            }
        }
        __syncthreads();
        const __half one = __float2half_rn(1.0f);
        const __half zero = __float2half_rn(0.0f);
        __half* A = ga.Asp[z];
#pragma unroll 1
        for (int p = 0; p < 16; p++) {
            int sid = p * 256 + tid;
            int d = sid & 127, gl = sid >> 7;  // gl in 0..31
            int jbase = j0 + gl * 4;
            int g = jbase >> 2;
            int b = g / 196, n = g - b * 196;
            int c = d0 + d;
            float v = 0.f;
#pragma unroll
            for (int t = 0; t < 4; t++) {
                float pre = S[d * 133 + gl * 4 + t];
                v += (pre - v) * 0.5f;
                bool s = (v >= 1.0f);
                A[(size_t)(jbase + t) * C_ + c] = s ? one : zero;
                if (z == 2) {
                    ga.vh[(size_t)(t * B_ + b) * 100352 + (c >> 6) * 12544 + n * 64 + (c & 63)] =
                        s ? 1.0f : 0.0f;
                }
                if (s) v = 0.f;
            }
        }
    }
}

// ---------------- host launch ----------------
extern "C" void kernel_launch(void* const* d_in, const int* in_sizes, int n_in,
                              void* d_out, int out_size) {
    const float *x, *qw, *kw, *vw, *ow, *ob;
    const float *qg, *qb, *qm, *qv, *kg, *kb, *km, *kvv, *vg, *vb, *vm, *vvv, *og, *obb, *om, *ov;
    if (n_in >= 5 && in_sizes[2] == 262144) {
        x = (const float*)d_in[0];
        qw = (const float*)d_in[1]; kw = (const float*)d_in[2];
        vw = (const float*)d_in[3]; ow = (const float*)d_in[4];
        ob = (const float*)d_in[5];
        qg = (const float*)d_in[6];  qb = (const float*)d_in[7];  qm = (const float*)d_in[8];  qv = (const float*)d_in[9];
        kg = (const float*)d_in[10]; kb = (const float*)d_in[11]; km = (const float*)d_in[12]; kvv = (const float*)d_in[13];
        vg = (const float*)d_in[14]; vb = (const float*)d_in[15]; vm = (const float*)d_in[16]; vvv = (const float*)d_in[17];
        og = (const float*)d_in[18]; obb = (const float*)d_in[19]; om = (const float*)d_in[20]; ov = (const float*)d_in[21];
    } else {
        x = (const float*)d_in[0];
        qw = (const float*)d_in[1];
        qg = (const float*)d_in[2];  qb = (const float*)d_in[3];  qm = (const float*)d_in[4];  qv = (const float*)d_in[5];
        kw = (const float*)d_in[6];
        kg = (const float*)d_in[7];  kb = (const float*)d_in[8];  km = (const float*)d_in[9];  kvv = (const float*)d_in[10];
        vw = (const float*)d_in[11];
        vg = (const float*)d_in[12]; vb = (const float*)d_in[13]; vm = (const float*)d_in[14]; vvv = (const float*)d_in[15];
        ow = (const float*)d_in[16]; ob = (const float*)d_in[17];
        og = (const float*)d_in[18]; obb = (const float*)d_in[19]; om = (const float*)d_in[20]; ov = (const float*)d_in[21];
    }

    float* out1 = (float*)d_out;
    float* out2 = (float*)d_out + TBCN_;

    __half *ax, *aq, *ak, *av, *wsp;
    unsigned char* kvs;
    cudaGetSymbolAddress((void**)&ax, g_ax);
    cudaGetSymbolAddress((void**)&aq, g_aq);
    cudaGetSymbolAddress((void**)&ak, g_ak);
    cudaGetSymbolAddress((void**)&av, g_av);
    cudaGetSymbolAddress((void**)&wsp, g_wsp);
    cudaGetSymbolAddress((void**)&kvs, g_kvs);

    cudaFuncSetAttribute(gemm_mma<false>, cudaFuncAttributeMaxDynamicSharedMemorySize, SMEM_DYN);
    cudaFuncSetAttribute(gemm_mma<true>, cudaFuncAttributeMaxDynamicSharedMemorySize, SMEM_DYN);

    // K0: weight fp16 2-limb splits
    split_w_kernel<<<4096, 256>>>(qw, kw, vw, ow, wsp);

    // K1: shortcut LIF -> Ax
    dim3 g1(B_, 32);
    lif_x_kernel<<<g1, 256>>>(x, ax);

    // G1: q/k/v GEMMs + fused BN+LIF epilogue -> Aq/Ak/Av spikes (+vh)
    GemmArgs a1;
    a1.Bact = ax;
    a1.W[0] = wsp; a1.W[1] = wsp + 2 * 262144; a1.W[2] = wsp + 4 * 262144;
    a1.g[0] = qg; a1.g[1] = kg; a1.g[2] = vg;
    a1.bb[0] = qb; a1.bb[1] = kb; a1.bb[2] = vb;
    a1.m[0] = qm; a1.m[1] = km; a1.m[2] = vm;
    a1.vv[0] = qv; a1.vv[1] = kvv; a1.vv[2] = vvv;
    a1.Asp[0] = aq; a1.Asp[1] = ak; a1.Asp[2] = av;
    a1.vh = out2;
    a1.kvs = nullptr; a1.out = nullptr; a1.bias = nullptr; a1.xid = nullptr;
    dim3 gg1(J_ / 128, C_ / 128, 3);
    gemm_mma<false><<<gg1, 256, SMEM_DYN>>>(a1);

    // K4: kv reduction + LIF (512 threads, 8-way n-split)
    dim3 g4(B_, 8);
    kv_lif_kernel<<<g4, 512>>>(ak, av, kvs);

    // G2: out GEMM (B = Aq masked by kvs in-smem) + bias + BN + residual (coalesced)
    GemmArgs a2;
    a2.Bact = aq;
    a2.W[0] = wsp + 6 * 262144; a2.W[1] = a2.W[2] = a2.W[0];
    a2.g[0] = a2.g[1] = a2.g[2] = og;
    a2.bb[0] = a2.bb[1] = a2.bb[2] = obb;
    a2.m[0] = a2.m[1] = a2.m[2] = om;
    a2.vv[0] = a2.vv[1] = a2.vv[2] = ov;
    a2.Asp[0] = a2.Asp[1] = a2.Asp[2] = nullptr;
    a2.vh = nullptr;
    a2.kvs = kvs;
    a2.out = out1;
    a2.bias = ob;
    a2.xid = x;
    dim3 gg2(J_ / 128, C_ / 128, 1);
    gemm_mma<true><<<gg2, 256, SMEM_DYN>>>(a2);
}

// round 17
// speedup vs baseline: 1.0266x; 1.0266x over previous
#include <cuda_runtime.h>
#include <cuda_fp16.h>
#include <stdint.h>

// Problem dims
#define T_ 4
#define B_ 32
#define C_ 512
#define N_ 196            // H*W
#define TB_ 128           // T*B
#define TBCN_ 12845056    // T*B*C*N
#define J_ 25088          // TB*N (GEMM columns), ordered j = (b*196+n)*4 + t

// ---------------- static scratch (allocation-free) ----------------
__device__ __half g_ax[TBCN_];    // x spikes  [j][c]
__device__ __half g_aq[TBCN_];    // q spikes  [j][c]
__device__ __half g_ak[TBCN_];    // k spikes  [j][c]
__device__ __half g_av[TBCN_];    // v spikes  [j][c]
__device__ __half g_wsp[4 * 2 * 262144];  // weight fp16 2-limb splits [mat][s][d*512+c]
__device__ unsigned char g_kvs[TB_ * C_];  // kv spikes [tb][c]

// ================= helpers =================
__device__ __forceinline__ uint32_t smem_u32(const void* p) {
    uint32_t a;
    asm("{ .reg .u64 t; cvta.to.shared.u64 t, %1; cvt.u32.u64 %0, t; }" : "=r"(a) : "l"(p));
    return a;
}
__device__ __forceinline__ void cp16(uint32_t dst, const void* src) {
    asm volatile("cp.async.cg.shared.global [%0], [%1], 16;" :: "r"(dst), "l"(src));
}
#define CP_COMMIT() asm volatile("cp.async.commit_group;" ::: "memory")
#define CP_WAIT1()  asm volatile("cp.async.wait_group 1;" ::: "memory")
#define CP_WAIT0()  asm volatile("cp.async.wait_group 0;" ::: "memory")

__device__ __forceinline__ void ldm_x4(uint32_t addr, uint32_t& r0, uint32_t& r1,
                                       uint32_t& r2, uint32_t& r3) {
    asm volatile("ldmatrix.sync.aligned.m8n8.x4.shared.b16 {%0,%1,%2,%3}, [%4];"
                 : "=r"(r0), "=r"(r1), "=r"(r2), "=r"(r3) : "r"(addr));
}
__device__ __forceinline__ void mma16816(float* c, const uint32_t* a, const uint32_t* b) {
    asm volatile("mma.sync.aligned.m16n8k16.row.col.f32.f16.f16.f32 "
                 "{%0,%1,%2,%3}, {%4,%5,%6,%7}, {%8,%9}, {%0,%1,%2,%3};"
                 : "+f"(c[0]), "+f"(c[1]), "+f"(c[2]), "+f"(c[3])
                 : "r"(a[0]), "r"(a[1]), "r"(a[2]), "r"(a[3]), "r"(b[0]), "r"(b[1]));
}

// smem tile geometry: row stride 40 fp16 (80B) -> ldmatrix conflict-free
#define RS 40
#define B_TILE_B (128 * RS * 2)          // 10240 bytes
#define A_TILE_B (128 * RS * 2)          // per split
#define NSPLIT 2
#define BUF_B (B_TILE_B + NSPLIT * A_TILE_B)  // 30720
#define SMEM_DYN 69632                   // >= 2*BUF_B (61440), >= 128*133*4 (68096), >= 16510*4 (66040)

// ---------------- K0: weight fp16 2-limb split ----------------
__global__ void split_w_kernel(const float* __restrict__ w0, const float* __restrict__ w1,
                               const float* __restrict__ w2, const float* __restrict__ w3,
                               __half* __restrict__ out) {
    int i = blockIdx.x * 256 + threadIdx.x;  // over 4*262144
    int mat = i >> 18;
    int k = i & 262143;
    const float* W = (mat == 0) ? w0 : (mat == 1) ? w1 : (mat == 2) ? w2 : w3;
    float w = W[k];
    __half f0 = __float2half_rn(w);
    float r = w - __half2float(f0);
    __half f1 = __float2half_rn(r);   // fp16 subnormals cover the residual range
    __half* o = out + (size_t)mat * 2 * 262144;
    o[k] = f0;
    o[262144 + k] = f1;
}

// ---------------- K1: shortcut LIF: x[t][b][c][n] -> Ax fp16 [j][c], j=(b*196+n)*4+t ----
__global__ __launch_bounds__(256) void lif_x_kernel(const float* __restrict__ x,
                                                    __half* __restrict__ Ax) {
    __shared__ float xt[16][197];
    __shared__ float vv[16][197];
    int b = blockIdx.x, c0 = blockIdx.y * 16, tid = threadIdx.x;
    for (int i = tid; i < 16 * 197; i += 256) ((float*)vv)[i] = 0.f;
    __syncthreads();
    const __half one = __float2half_rn(1.0f);
    const __half zero = __float2half_rn(0.0f);
    for (int t = 0; t < T_; t++) {
        for (int i = tid; i < 16 * 196; i += 256) {
            int cc = i / 196, n = i - cc * 196;
            xt[cc][n] = x[(size_t)(((t * B_ + b) * C_) + c0 + cc) * N_ + n];
        }
        __syncthreads();
        for (int i = tid; i < 16 * 196; i += 256) {
            int n = i >> 4, cc = i & 15;
            float v = vv[cc][n];
            v += (xt[cc][n] - v) * 0.5f;
            bool s = (v >= 1.0f);
            int j = (b * 196 + n) * 4 + t;
            Ax[(size_t)j * C_ + c0 + cc] = s ? one : zero;
            vv[cc][n] = s ? 0.f : v;
        }
        __syncthreads();
    }
}

// ---------------- K4: kv = sum_n(k&v), LIF over t -> kvs[tb][c] ----------------
// R15 version (proven 29.8us): 256 threads, 64c x 4q, fixed 49-trip unrolled loop.
__global__ __launch_bounds__(256) void kv_lif_kernel(const __half* __restrict__ Ak,
                                                     const __half* __restrict__ Av,
                                                     unsigned char* __restrict__ kvs) {
    __shared__ int red[4][4][64];  // [nq][t][c]
    int b = blockIdx.x, c0 = blockIdx.y * 64;
    int cc = threadIdx.x & 63, q = threadIdx.x >> 6;
    const unsigned short* ak = (const unsigned short*)Ak;
    const unsigned short* av = (const unsigned short*)Av;
    int cnt[4] = {0, 0, 0, 0};
    int nbeg = q * 49;
#pragma unroll 7
    for (int n = nbeg; n < nbeg + 49; n++) {
        size_t base = (size_t)((b * 196 + n) * 4) * C_ + c0 + cc;
#pragma unroll
        for (int t = 0; t < 4; t++)
            cnt[t] += ((ak[base + t * C_] & av[base + t * C_]) != 0);
    }
#pragma unroll
    for (int t = 0; t < 4; t++) red[q][t][cc] = cnt[t];
    __syncthreads();
    if (q == 0) {
        float v = 0.f;
#pragma unroll
        for (int t = 0; t < 4; t++) {
            float pre = (float)(red[0][t][cc] + red[1][t][cc] + red[2][t][cc] + red[3][t][cc]);
            v += (pre - v) * 0.5f;
            bool s = (v >= 1.0f);
            kvs[(t * B_ + b) * C_ + c0 + cc] = (unsigned char)s;
            if (s) v = 0.f;
        }
    }
}

// ---------------- HMMA GEMM ----------------
// QKV (!OUT): P = W_z * Ax, BN, then fused 4-step LIF over adjacent t columns;
//             writes fp16 spikes to Asp[z] (+ vh for z==2).
// OUT:        B operand = Aq masked in-smem by kvs; epilogue BN+bias+residual -> out,
//             smem-staged so gmem loads/stores are n-coalesced.
struct GemmArgs {
    const __half* Bact;
    const __half* W[3];
    const float* g[3];
    const float* bb[3];
    const float* m[3];
    const float* vv[3];
    __half* Asp[3];            // QKV: spike outputs
    float* vh;                 // QKV z==2
    const unsigned char* kvs;  // OUT
    float* out;                // OUT
    const float* bias;         // OUT
    const float* xid;          // OUT
};

template <bool OUT>
__global__ __launch_bounds__(256) void gemm_mma(GemmArgs ga) {
    extern __shared__ char sm[];
    __shared__ float scs[128];
    __shared__ float shs[128];
    uint32_t sb = smem_u32(sm);
    int tid = threadIdx.x, lane = tid & 31, wid = tid >> 5;
    int wd = wid >> 2, wj = wid & 3;            // warps: 2 (d) x 4 (j)
    int j0 = blockIdx.x * 128, d0 = blockIdx.y * 128, z = blockIdx.z;
    const __half* __restrict__ Wz = ga.W[z];
    const __half* __restrict__ Ba = ga.Bact;

    // BN scale/shift
    if (tid < 128) {
        int d = d0 + tid;
        float sc = ga.g[z][d] / sqrtf(ga.vv[z][d] + 1e-5f);
        float sh = ga.bb[z][d] - ga.m[z][d] * sc;
        if (OUT) sh += ga.bias[d] * sc;
        scs[tid] = sc;
        shs[tid] = sh;
    }

    float acc[4][4][4];
#pragma unroll
    for (int a = 0; a < 4; a++)
#pragma unroll
        for (int b = 0; b < 4; b++)
#pragma unroll
            for (int c = 0; c < 4; c++) acc[a][b][c] = 0.f;

    int brow = tid >> 2, bseg = tid & 3;  // B slots: rows brow, brow+64; 8 cols each

    // OUT: per-thread tb of its two B rows (constant across chunks)
    int tb_r[2];
    if (OUT) {
#pragma unroll
        for (int i = 0; i < 2; i++) {
            int j = j0 + brow + i * 64;
            int t = j & 3, g = j >> 2, b = g / 196;
            tb_r[i] = t * B_ + b;
        }
    }

    auto load_chunk = [&](int buf, int it) {
        int c0 = it * 32;
        uint32_t base = sb + buf * BUF_B;
#pragma unroll
        for (int i = 0; i < 2; i++) {
            int row = brow + i * 64;
            cp16(base + row * (RS * 2) + bseg * 16,
                 Ba + (size_t)(j0 + row) * C_ + c0 + bseg * 8);
        }
#pragma unroll
        for (int i = 0; i < 2 * NSPLIT; i++) {
            int e = tid + i * 256;
            int s = e >> 9;
            int row = (e >> 2) & 127;
            int seg = e & 3;
            cp16(base + B_TILE_B + s * A_TILE_B + row * (RS * 2) + seg * 16,
                 Wz + (size_t)s * 262144 + (size_t)(d0 + row) * C_ + c0 + seg * 8);
        }
    };

    // ldmatrix address patterns
    int sub = lane >> 3, l7 = lane & 7;
    int a_r = (sub & 1) * 8 + l7, a_c2 = (sub >> 1) * 8;
    int b_r = (sub >> 1) * 8 + l7, b_c2 = (sub & 1) * 8;

    load_chunk(0, 0);
    CP_COMMIT();

    for (int it = 0; it < 16; it++) {
        if (it < 15) {
            load_chunk((it + 1) & 1, it + 1);
            CP_COMMIT();
            CP_WAIT1();
        } else {
            CP_WAIT0();
        }

        // OUT: mask own B slots with kvs (this thread's own cp.async data, now complete)
        if (OUT) {
            int c0 = it * 32;
#pragma unroll
            for (int i = 0; i < 2; i++) {
                int row = brow + i * 64;
                const unsigned char* kp = ga.kvs + tb_r[i] * C_ + c0 + bseg * 8;
                uint32_t k0 = *(const uint32_t*)kp;
                uint32_t k1 = *(const uint32_t*)(kp + 4);
                uint4* sp = (uint4*)(sm + (it & 1) * BUF_B + row * (RS * 2) + bseg * 16);
                uint4 w = *sp;
                w.x &= ((k0 & 0xFFu) ? 0xFFFFu : 0u) | ((k0 & 0xFF00u) ? 0xFFFF0000u : 0u);
                w.y &= ((k0 & 0xFF0000u) ? 0xFFFFu : 0u) | ((k0 & 0xFF000000u) ? 0xFFFF0000u : 0u);
                w.z &= ((k1 & 0xFFu) ? 0xFFFFu : 0u) | ((k1 & 0xFF00u) ? 0xFFFF0000u : 0u);
                w.w &= ((k1 & 0xFF0000u) ? 0xFFFFu : 0u) | ((k1 & 0xFF000000u) ? 0xFFFF0000u : 0u);
                *sp = w;
            }
        }
        __syncthreads();

        uint32_t base = sb + (it & 1) * BUF_B;
        uint32_t bB = base;
        uint32_t bA = base + B_TILE_B;

        uint32_t bf[2][4][2];
#pragma unroll
        for (int k16 = 0; k16 < 2; k16++)
#pragma unroll
            for (int np = 0; np < 2; np++) {
                int row = wj * 32 + np * 16 + b_r;
                int col = k16 * 16 + b_c2;
                uint32_t addr = bB + row * (RS * 2) + col * 2;
                ldm_x4(addr, bf[k16][np * 2][0], bf[k16][np * 2][1],
                       bf[k16][np * 2 + 1][0], bf[k16][np * 2 + 1][1]);
            }

#pragma unroll
        for (int s = 0; s < NSPLIT; s++) {
#pragma unroll
            for (int k16 = 0; k16 < 2; k16++) {
#pragma unroll
                for (int mi = 0; mi < 4; mi++) {
                    uint32_t af[4];
                    int row = wd * 64 + mi * 16 + a_r;
                    int col = k16 * 16 + a_c2;
                    uint32_t addr = bA + s * A_TILE_B + row * (RS * 2) + col * 2;
                    ldm_x4(addr, af[0], af[1], af[2], af[3]);
#pragma unroll
                    for (int ni = 0; ni < 4; ni++)
                        mma16816(acc[mi][ni], af, bf[k16][ni]);
                }
            }
        }
        __syncthreads();
    }

    // ---------------- epilogue ----------------
    int r = lane >> 2, cq = (lane & 3) * 2;
    if (OUT) {
        // Stage BN'd values to smem S2[(t*32+g)*129 + d] (read conflict-free:
        // 129 % 32 == 1), then write out/xid n-coalesced (lane = g -> consecutive n).
        float* S2 = (float*)sm;
#pragma unroll
        for (int mi = 0; mi < 4; mi++) {
            int dl0 = wd * 64 + mi * 16 + r;
#pragma unroll
            for (int ni = 0; ni < 4; ni++) {
                int jjl = wj * 32 + ni * 8 + cq;
#pragma unroll
                for (int e = 0; e < 4; e++) {
                    int dd = dl0 + (e >> 1) * 8;
                    int jl = jjl + (e & 1);
                    float v = acc[mi][ni][e] * scs[dd] + shs[dd];
                    int t = jl & 3, g = jl >> 2;
                    S2[(t * 32 + g) * 129 + dd] = v;
                }
            }
        }
        __syncthreads();
        const float* xid = ga.xid;
        float* o = ga.out;
        int g0 = blockIdx.x * 32;
        int gg = g0 + lane;
        int bb2 = gg / 196;
        int nn = gg - bb2 * 196;
#pragma unroll 8
        for (int i = 0; i < 64; i++) {
            int idx = i * 8 + wid;        // 512 (d,t) pairs over 8 warps
            int d = idx >> 2, t = idx & 3;
            float v = S2[(t * 32 + lane) * 129 + d];
            size_t gi = (size_t)((t * B_ + bb2) * C_ + d0 + d) * N_ + nn;
            o[gi] = v + xid[gi];
        }
    } else {
        // stage BN'd pre-acts to smem [d][j_local], stride 133 (odd -> LIF reads
        // conflict-free). Scalar stores only (odd stride => float2 would misalign).
        float* S = (float*)sm;
#pragma unroll
        for (int mi = 0; mi < 4; mi++) {
            int dl0 = wd * 64 + mi * 16 + r;
#pragma unroll
            for (int ni = 0; ni < 4; ni++) {
                int jj = wj * 32 + ni * 8 + cq;
                S[dl0 * 133 + jj] = acc[mi][ni][0] * scs[dl0] + shs[dl0];
                S[dl0 * 133 + jj + 1] = acc[mi][ni][1] * scs[dl0] + shs[dl0];
                S[(dl0 + 8) * 133 + jj] = acc[mi][ni][2] * scs[dl0 + 8] + shs[dl0 + 8];
                S[(dl0 + 8) * 133 + jj + 1] = acc[mi][ni][3] * scs[dl0 + 8] + shs[dl0 + 8];
            }
        }
        __syncthreads();
        const __half one = __float2half_rn(1.0f);
        const __half zero = __float2half_rn(0.0f);
        __half* A = ga.Asp[z];
#pragma unroll 1
        for (int p = 0; p < 16; p++) {
            int sid = p * 256 + tid;
            int d = sid & 127, gl = sid >> 7;  // gl in 0..31
            int jbase = j0 + gl * 4;
            int g = jbase >> 2;
            int b = g / 196, n = g - b * 196;
            int c = d0 + d;
            float v = 0.f;
#pragma unroll
            for (int t = 0; t < 4; t++) {
                float pre = S[d * 133 + gl * 4 + t];
                v += (pre - v) * 0.5f;
                bool s = (v >= 1.0f);
                A[(size_t)(jbase + t) * C_ + c] = s ? one : zero;
                if (z == 2) {
                    ga.vh[(size_t)(t * B_ + b) * 100352 + (c >> 6) * 12544 + n * 64 + (c & 63)] =
                        s ? 1.0f : 0.0f;
                }
                if (s) v = 0.f;
            }
        }
    }
}

// ---------------- host launch ----------------
extern "C" void kernel_launch(void* const* d_in, const int* in_sizes, int n_in,
                              void* d_out, int out_size) {
    const float *x, *qw, *kw, *vw, *ow, *ob;
    const float *qg, *qb, *qm, *qv, *kg, *kb, *km, *kvv, *vg, *vb, *vm, *vvv, *og, *obb, *om, *ov;
    if (n_in >= 5 && in_sizes[2] == 262144) {
        x = (const float*)d_in[0];
        qw = (const float*)d_in[1]; kw = (const float*)d_in[2];
        vw = (const float*)d_in[3]; ow = (const float*)d_in[4];
        ob = (const float*)d_in[5];
        qg = (const float*)d_in[6];  qb = (const float*)d_in[7];  qm = (const float*)d_in[8];  qv = (const float*)d_in[9];
        kg = (const float*)d_in[10]; kb = (const float*)d_in[11]; km = (const float*)d_in[12]; kvv = (const float*)d_in[13];
        vg = (const float*)d_in[14]; vb = (const float*)d_in[15]; vm = (const float*)d_in[16]; vvv = (const float*)d_in[17];
        og = (const float*)d_in[18]; obb = (const float*)d_in[19]; om = (const float*)d_in[20]; ov = (const float*)d_in[21];
    } else {
        x = (const float*)d_in[0];
        qw = (const float*)d_in[1];
        qg = (const float*)d_in[2];  qb = (const float*)d_in[3];  qm = (const float*)d_in[4];  qv = (const float*)d_in[5];
        kw = (const float*)d_in[6];
        kg = (const float*)d_in[7];  kb = (const float*)d_in[8];  km = (const float*)d_in[9];  kvv = (const float*)d_in[10];
        vw = (const float*)d_in[11];
        vg = (const float*)d_in[12]; vb = (const float*)d_in[13]; vm = (const float*)d_in[14]; vvv = (const float*)d_in[15];
        ow = (const float*)d_in[16]; ob = (const float*)d_in[17];
        og = (const float*)d_in[18]; obb = (const float*)d_in[19]; om = (const float*)d_in[20]; ov = (const float*)d_in[21];
    }

    float* out1 = (float*)d_out;
    float* out2 = (float*)d_out + TBCN_;

    __half *ax, *aq, *ak, *av, *wsp;
    unsigned char* kvs;
    cudaGetSymbolAddress((void**)&ax, g_ax);
    cudaGetSymbolAddress((void**)&aq, g_aq);
    cudaGetSymbolAddress((void**)&ak, g_ak);
    cudaGetSymbolAddress((void**)&av, g_av);
    cudaGetSymbolAddress((void**)&wsp, g_wsp);
    cudaGetSymbolAddress((void**)&kvs, g_kvs);

    cudaFuncSetAttribute(gemm_mma<false>, cudaFuncAttributeMaxDynamicSharedMemorySize, SMEM_DYN);
    cudaFuncSetAttribute(gemm_mma<true>, cudaFuncAttributeMaxDynamicSharedMemorySize, SMEM_DYN);

    // K0: weight fp16 2-limb splits
    split_w_kernel<<<4096, 256>>>(qw, kw, vw, ow, wsp);

    // K1: shortcut LIF -> Ax
    dim3 g1(B_, 32);
    lif_x_kernel<<<g1, 256>>>(x, ax);

    // G1: q/k/v GEMMs + fused BN+LIF epilogue -> Aq/Ak/Av spikes (+vh)
    GemmArgs a1;
    a1.Bact = ax;
    a1.W[0] = wsp; a1.W[1] = wsp + 2 * 262144; a1.W[2] = wsp + 4 * 262144;
    a1.g[0] = qg; a1.g[1] = kg; a1.g[2] = vg;
    a1.bb[0] = qb; a1.bb[1] = kb; a1.bb[2] = vb;
    a1.m[0] = qm; a1.m[1] = km; a1.m[2] = vm;
    a1.vv[0] = qv; a1.vv[1] = kvv; a1.vv[2] = vvv;
    a1.Asp[0] = aq; a1.Asp[1] = ak; a1.Asp[2] = av;
    a1.vh = out2;
    a1.kvs = nullptr; a1.out = nullptr; a1.bias = nullptr; a1.xid = nullptr;
    dim3 gg1(J_ / 128, C_ / 128, 3);
    gemm_mma<false><<<gg1, 256, SMEM_DYN>>>(a1);

    // K4: kv reduction + LIF (reverted to proven R15 config)
    dim3 g4(B_, 8);
    kv_lif_kernel<<<g4, 256>>>(ak, av, kvs);

    // G2: out GEMM (B = Aq masked by kvs in-smem) + bias + BN + residual (coalesced)
    GemmArgs a2;
    a2.Bact = aq;
    a2.W[0] = wsp + 6 * 262144; a2.W[1] = a2.W[2] = a2.W[0];
    a2.g[0] = a2.g[1] = a2.g[2] = og;
    a2.bb[0] = a2.bb[1] = a2.bb[2] = obb;
    a2.m[0] = a2.m[1] = a2.m[2] = om;
    a2.vv[0] = a2.vv[1] = a2.vv[2] = ov;
    a2.Asp[0] = a2.Asp[1] = a2.Asp[2] = nullptr;
    a2.vh = nullptr;
    a2.kvs = kvs;
    a2.out = out1;
    a2.bias = ob;
    a2.xid = x;
    dim3 gg2(J_ / 128, C_ / 128, 1);
    gemm_mma<true><<<gg2, 256, SMEM_DYN>>>(a2);
}